// round 3
// baseline (speedup 1.0000x reference)
#include <cuda_runtime.h>
#include <math.h>

// ---------------- problem constants ----------------
#define B_STRIDE   (128*262144)   // per-batch stride in feats
#define CH_STRIDE  262144         // per-channel stride (64^3)
#define SIG_THR    (-1.0986122886681098f)  // ln(0.25/0.75): sigmoid(x)>0.25 <=> x>thr
#define TEMP_INV   10.0f

#define NROWS_VOX  12800          // 2*64*100 rows per (anchor|positive)
#define ROW_VEC_A  25600
#define ROW_VEC_P  25728
#define NROWS      25856          // 2*12800 + 2*128

// ---------------- scratch (static device globals; no allocations) ----------------
__device__ float g_PM[2][2][128][64];   // [which][b][c][spatial_patch] patch means
__device__ int   g_pcount[128];         // [b*64 + spatial_patch] edge voxel counts
__device__ int   g_vidx[100];           // decoded voxel indices
__device__ float g_W1t[128*128];        // W1^T  (k-major)
__device__ float g_W2t[128*64];         // W2^T
__device__ float g_X[NROWS*128];        // projector inputs
__device__ float g_Y[NROWS*64];         // normalized projector outputs
__device__ float g_voxloss[128];        // per (b,n) voxel loss

// ---------------- tiny init kernels ----------------
__global__ void rc_zero_kernel() {
    if (threadIdx.x < 128) g_pcount[threadIdx.x] = 0;
}

// voxel_idx may arrive as int64 or int32 depending on jax x64 config.
// int64 little-endian: odd 32-bit words are all zero (values < 4096).
__global__ void rc_prep_vidx_kernel(const int* __restrict__ raw) {
    __shared__ int nz;
    if (threadIdx.x == 0) nz = 0;
    __syncthreads();
    if (threadIdx.x < 100 && raw[threadIdx.x] == 0) atomicAdd(&nz, 1);
    __syncthreads();
    bool is64 = (nz >= 40);
    if (threadIdx.x < 100)
        g_vidx[threadIdx.x] = is64 ? raw[2*threadIdx.x] : raw[threadIdx.x];
}

__global__ void rc_transpose_w_kernel(const float* __restrict__ w1,
                                      const float* __restrict__ w2) {
    int idx = blockIdx.x*256 + threadIdx.x;
    if (idx < 16384) {            // W1 [128,128]
        int j = idx >> 7, k = idx & 127;
        g_W1t[k*128 + j] = w1[idx];
    } else if (idx < 24576) {     // W2 [64,128]
        int t = idx - 16384;
        int j = t >> 7, k = t & 127;
        g_W2t[k*64 + j] = w2[t];
    }
}

// ---------------- fused conv1(3x3x3,128->32)+ReLU+conv2(1x1)+sigmoid-threshold ----------------
// Tile 16x(x) * 4(y) * 8(z); 256 threads, each owns a z-adjacent voxel PAIR and all 32
// output channels, accumulated as packed f32x2. Weights staged in smem as duplicated
// 64-bit pairs so the inner loop is 1 broadcast LDS.64 + 1 fma.rn.f32x2 per (oc).
// Issue-floor analysis: 906M warp-FFMA2 @ rt_SMSP=2 -> ~3.06M cyc chip-wide; the LDS.64
// stream fits in the alternate issue slots, so this is at the FFMA2 floor.
__global__ __launch_bounds__(256)
void rc_conv_mask_kernel(const float* __restrict__ in,
                         const float* __restrict__ w1,
                         const float* __restrict__ b1,
                         const float* __restrict__ w2,
                         const float* __restrict__ b2) {
    __shared__ float              in_s[4*1080];      // [cl][lz(10)][ly(6)][lx(18)]
    __shared__ unsigned long long w_s[4*27*32];      // [(cl*27+k)*32 + oc], value duplicated

    const int tid = threadIdx.x;
    const int tx = tid & 15, ty = (tid >> 4) & 3, tz = tid >> 6;   // tz in [0,4)
    const int b  = blockIdx.z >> 3, zt = blockIdx.z & 7;
    const int x0 = blockIdx.x * 16, y0 = blockIdx.y * 4, z0 = zt * 8;

    const float* src = in + b * B_STRIDE;

    unsigned long long acc[32];
#pragma unroll
    for (int oc = 0; oc < 32; oc++) acc[oc] = 0ull;

    for (int cc0 = 0; cc0 < 128; cc0 += 4) {
        // stage input tile with halo (zero padded)
        for (int idx = tid; idx < 4*1080; idx += 256) {
            int cl = idx / 1080; int rem = idx - cl*1080;
            int lz = rem / 108;  int r2  = rem - lz*108;
            int ly = r2 / 18;    int lx  = r2 - ly*18;
            int gz = z0 - 1 + lz, gy = y0 - 1 + ly, gx = x0 - 1 + lx;
            float v = 0.f;
            if ((unsigned)gz < 64u && (unsigned)gy < 64u && (unsigned)gx < 64u)
                v = src[(cc0 + cl)*CH_STRIDE + gz*4096 + gy*64 + gx];
            in_s[idx] = v;
        }
        // stage weights, duplicated into both 32-bit halves
        for (int idx = tid; idx < 3456; idx += 256) {
            int oc = idx / 108; int rem = idx - oc*108;
            int cl = rem / 27;  int k   = rem - cl*27;
            unsigned int u = __float_as_uint(w1[oc*3456 + (cc0 + cl)*27 + k]);
            w_s[(cl*27 + k)*32 + oc] = ((unsigned long long)u << 32) | u;
        }
        __syncthreads();

#pragma unroll 1
        for (int cl = 0; cl < 4; cl++) {
            const float* ibase = &in_s[cl*1080 + (2*tz)*108 + ty*18 + tx];
            const unsigned long long* wbase = &w_s[cl*27*32];
#pragma unroll 1
            for (int kz = 0; kz < 3; kz++) {
#pragma unroll
                for (int ky = 0; ky < 3; ky++) {
                    const float* ip = ibase + kz*108 + ky*18;
                    const unsigned long long* wk = wbase + (kz*9 + ky*3)*32;
#pragma unroll
                    for (int kx = 0; kx < 3; kx++) {
                        float a0 = ip[kx];
                        float a1 = ip[kx + 108];
                        unsigned long long av;
                        asm("mov.b64 %0, {%1, %2};"
                            : "=l"(av) : "r"(__float_as_uint(a0)), "r"(__float_as_uint(a1)));
                        const unsigned long long* wkk = wk + kx*32;
#pragma unroll
                        for (int oc = 0; oc < 32; oc++)
                            asm("fma.rn.f32x2 %0, %1, %2, %0;"
                                : "+l"(acc[oc]) : "l"(av), "l"(wkk[oc]));
                    }
                }
            }
        }
        __syncthreads();
    }

    // epilogue: bias+ReLU, 1x1 conv2, threshold, per-patch count
    float v0 = b2[0], v1 = b2[0];
#pragma unroll
    for (int oc = 0; oc < 32; oc++) {
        float lo = __uint_as_float((unsigned)(acc[oc] & 0xffffffffu));
        float hi = __uint_as_float((unsigned)(acc[oc] >> 32));
        float bb = b1[oc], ww = w2[oc];
        v0 += fmaxf(lo + bb, 0.f) * ww;
        v1 += fmaxf(hi + bb, 0.f) * ww;
    }
    unsigned bal0 = __ballot_sync(0xffffffffu, v0 > SIG_THR);
    unsigned bal1 = __ballot_sync(0xffffffffu, v1 > SIG_THR);
    if ((tid & 31) == 0) {
        int patch = (z0 >> 4)*16 + (y0 >> 4)*4 + (x0 >> 4);  // whole tile in one patch
        atomicAdd(&g_pcount[b*64 + patch], __popc(bal0) + __popc(bal1));
    }
}

// ---------------- per (which,b,channel,spatial-patch) means ----------------
__global__ void rc_patchmean_kernel(const float* __restrict__ a,
                                    const float* __restrict__ p) {
    int s = blockIdx.x, c = blockIdx.y;
    int which = blockIdx.z >> 1, b = blockIdx.z & 1;
    const float* src = (which == 0 ? a : p) + b*B_STRIDE + c*CH_STRIDE;
    int dp = s >> 4, hp = (s >> 2) & 3, wp = s & 3;
    const float* base = src + (dp*16)*4096 + (hp*16)*64 + wp*16;
    float sum = 0.f;
    for (int v = threadIdx.x; v < 4096; v += 128) {
        int pz = v >> 8, py = (v >> 4) & 15, px = v & 15;
        sum += base[pz*4096 + py*64 + px];
    }
    __shared__ float red[128];
    red[threadIdx.x] = sum; __syncthreads();
    for (int st = 64; st > 0; st >>= 1) {
        if (threadIdx.x < st) red[threadIdx.x] += red[threadIdx.x + st];
        __syncthreads();
    }
    if (threadIdx.x == 0) g_PM[which][b][c][s] = red[0] * (1.f/4096.f);
}

// ---------------- voxel gather: replicates the channel/patch-mixing view ----------------
// reference view(B,-1,C,P,P,P) mixes channels & spatial patches:
//   row (b,n) channel c' -> real channel 2n + (c'>>6), spatial patch c'&63
__global__ void rc_gather_vox_kernel(const float* __restrict__ a,
                                     const float* __restrict__ p) {
    int i = blockIdx.x, n = blockIdx.y;
    int which = blockIdx.z >> 1, b = blockIdx.z & 1;
    int c = threadIdx.x;                       // c' in [0,128)
    const float* src = (which == 0 ? a : p) + b*B_STRIDE;
    int v = g_vidx[i];
    int pz = v >> 8, py = (v >> 4) & 15, px = v & 15;
    int ch = 2*n + (c >> 6);
    int s  = c & 63;
    int z = (s >> 4)*16 + pz, y = ((s >> 2) & 3)*16 + py, x = (s & 3)*16 + px;
    int row = which*NROWS_VOX + (b*64 + n)*100 + i;
    g_X[row*128 + c] = src[ch*CH_STRIDE + z*4096 + y*64 + x];
}

__global__ void rc_gather_vec_kernel() {
    int n = blockIdx.x, b = blockIdx.y, which = blockIdx.z;
    int c = threadIdx.x;
    int row = ROW_VEC_A + which*128 + b*64 + n;
    g_X[row*128 + c] = g_PM[which][b][2*n + (c >> 6)][c & 63];
}

// ---------------- projector (128->128 ReLU ->64) + L2 normalize, 16 rows/block ----------------
__global__ __launch_bounds__(128)
void rc_projector_kernel(const float* __restrict__ b1v, const float* __restrict__ b2v) {
    __shared__ float Xs[16*128];
    __shared__ float Hs[16*128];
    __shared__ float Ys[16*64];
    __shared__ float nrm[16];
    int r0 = blockIdx.x * 16;
    int j = threadIdx.x;

    for (int idx = j; idx < 2048; idx += 128) Xs[idx] = g_X[r0*128 + idx];
    __syncthreads();
    {
        float acc[16];
        float bj = b1v[j];
#pragma unroll
        for (int r = 0; r < 16; r++) acc[r] = bj;
        for (int k = 0; k < 128; k++) {
            float w = g_W1t[k*128 + j];
#pragma unroll
            for (int r = 0; r < 16; r++) acc[r] += w * Xs[r*128 + k];
        }
#pragma unroll
        for (int r = 0; r < 16; r++) Hs[r*128 + j] = fmaxf(acc[r], 0.f);
    }
    __syncthreads();
    if (j < 64) {
        float acc[16];
        float bj = b2v[j];
#pragma unroll
        for (int r = 0; r < 16; r++) acc[r] = bj;
        for (int k = 0; k < 128; k++) {
            float w = g_W2t[k*64 + j];
#pragma unroll
            for (int r = 0; r < 16; r++) acc[r] += w * Hs[r*128 + k];
        }
#pragma unroll
        for (int r = 0; r < 16; r++) Ys[r*64 + j] = acc[r];
    }
    __syncthreads();
    if (j < 16) {
        float ss = 0.f;
#pragma unroll
        for (int d = 0; d < 64; d++) { float y = Ys[j*64 + d]; ss += y*y; }
        nrm[j] = 1.f / fmaxf(sqrtf(ss), 1e-12f);
    }
    __syncthreads();
    for (int idx = j; idx < 1024; idx += 128) {
        int r = idx >> 6;
        g_Y[(r0 + r)*64 + (idx & 63)] = Ys[idx] * nrm[r];
    }
}

// ---------------- voxel loss: 100x100 sim, online logsumexp, mean(lse - diag) ----------------
__global__ __launch_bounds__(128)
void rc_voxloss_kernel() {
    __shared__ float Ps[100*64];
    __shared__ float red[128];
    int bn = blockIdx.x;
    int rowA = bn*100, rowP = NROWS_VOX + bn*100;
    for (int idx = threadIdx.x; idx < 6400; idx += 128)
        Ps[idx] = g_Y[rowP*64 + idx];
    __syncthreads();
    int i = threadIdx.x;
    float contrib = 0.f;
    if (i < 100) {
        float areg[64];
        const float4* ar = (const float4*)&g_Y[(rowA + i)*64];
#pragma unroll
        for (int q = 0; q < 16; q++) {
            float4 t = ar[q];
            areg[4*q] = t.x; areg[4*q+1] = t.y; areg[4*q+2] = t.z; areg[4*q+3] = t.w;
        }
        float m = -INFINITY, ssum = 0.f, dv = 0.f;
        for (int jj = 0; jj < 100; jj++) {
            const float* pj = &Ps[jj*64];
            float v = 0.f;
#pragma unroll
            for (int d = 0; d < 64; d++) v += areg[d] * pj[d];
            v *= TEMP_INV;
            if (jj == i) dv = v;
            if (v > m) { ssum = ssum * __expf(m - v) + 1.0f; m = v; }
            else       { ssum += __expf(v - m); }
        }
        contrib = (m + __logf(ssum)) - dv;
    }
    red[threadIdx.x] = contrib; __syncthreads();
    for (int st = 64; st > 0; st >>= 1) {
        if (threadIdx.x < st) red[threadIdx.x] += red[threadIdx.x + st];
        __syncthreads();
    }
    if (threadIdx.x == 0) g_voxloss[bn] = red[0] * (1.f/100.f);
}

// ---------------- final combine ----------------
__global__ void rc_final_kernel(const float* __restrict__ lw, float* __restrict__ out) {
    __shared__ float rp[128], rv[128], rc[128];
    int bn = threadIdx.x;
    float ratio  = (float)g_pcount[bn] * (1.f/4096.f);
    float mvox   = ratio > 0.6f ? 1.f : 0.f;
    float mpatch = ratio < 0.4f ? 1.f : 0.f;
    float dot = 0.f;
    const float* ya = &g_Y[(ROW_VEC_A + bn)*64];
    const float* yp = &g_Y[(ROW_VEC_P + bn)*64];
#pragma unroll
    for (int d = 0; d < 64; d++) dot += ya[d] * yp[d];
    float pl = -dot * TEMP_INV;
    rp[bn] = pl * mpatch;
    rv[bn] = g_voxloss[bn] * mvox;
    rc[bn] = mpatch + mvox;
    __syncthreads();
    for (int st = 64; st > 0; st >>= 1) {
        if (bn < st) { rp[bn] += rp[bn+st]; rv[bn] += rv[bn+st]; rc[bn] += rc[bn+st]; }
        __syncthreads();
    }
    if (bn == 0) {
        float total = lw[0]*rp[0] + lw[1]*rv[0];
        float valid = rc[0];
        out[0] = (valid > 0.f) ? total / fmaxf(valid, 1.f) : 0.f;
    }
}

// ---------------- launch ----------------
extern "C" void kernel_launch(void* const* d_in, const int* in_sizes, int n_in,
                              void* d_out, int out_size) {
    const float* anchor   = (const float*)d_in[0];
    const float* positive = (const float*)d_in[1];
    const float* c1w = (const float*)d_in[2];
    const float* c1b = (const float*)d_in[3];
    const float* c2w = (const float*)d_in[4];
    const float* c2b = (const float*)d_in[5];
    const float* w1  = (const float*)d_in[6];
    const float* b1  = (const float*)d_in[7];
    const float* w2  = (const float*)d_in[8];
    const float* b2  = (const float*)d_in[9];
    const float* lw  = (const float*)d_in[10];
    const int*   vix = (const int*)d_in[11];   // int32 or int64; decoded on device

    rc_zero_kernel<<<1, 128>>>();
    rc_prep_vidx_kernel<<<1, 128>>>(vix);
    rc_transpose_w_kernel<<<96, 256>>>(w1, w2);

    rc_conv_mask_kernel<<<dim3(4, 16, 16), 256>>>(anchor, c1w, c1b, c2w, c2b);
    rc_patchmean_kernel<<<dim3(64, 128, 4), 128>>>(anchor, positive);
    rc_gather_vox_kernel<<<dim3(100, 64, 4), 128>>>(anchor, positive);
    rc_gather_vec_kernel<<<dim3(64, 2, 2), 128>>>();

    rc_projector_kernel<<<NROWS/16, 128>>>(b1, b2);
    rc_voxloss_kernel<<<128, 128>>>();
    rc_final_kernel<<<1, 128>>>(lw, (float*)d_out);
}

// round 15
// speedup vs baseline: 1.2952x; 1.2952x over previous
#include <cuda_runtime.h>
#include <math.h>

// ---------------- problem constants ----------------
#define B_STRIDE   (128*262144)   // per-batch stride in feats
#define CH_STRIDE  262144         // per-channel stride (64^3)
#define SIG_THR    (-1.0986122886681098f)  // ln(0.25/0.75): sigmoid(x)>0.25 <=> x>thr
#define TEMP_INV   10.0f

#define NROWS_VOX  12800          // 2*64*100 rows per (anchor|positive)
#define ROW_VEC_A  25600
#define ROW_VEC_P  25728
#define NROWS      25856          // 2*12800 + 2*128

typedef unsigned long long ull;

// ---------------- scratch (static device globals; no allocations) ----------------
__device__ float g_PM[2][2][128][64];   // [which][b][c][spatial_patch] patch means
__device__ int   g_pcount[128];         // [b*64 + spatial_patch] edge voxel counts
__device__ int   g_vidx[100];           // decoded voxel indices
__device__ float g_W1t[128*128];        // W1^T  (k-major)
__device__ float g_W2t[128*64];         // W2^T
__device__ float g_X[NROWS*128];        // projector inputs
__device__ float g_Y[NROWS*64];         // normalized projector outputs
__device__ float g_voxloss[128];        // per (b,n) voxel loss

// ---------------- tiny init kernels ----------------
__global__ void rc_zero_kernel() {
    if (threadIdx.x < 128) g_pcount[threadIdx.x] = 0;
}

// voxel_idx may arrive as int64 or int32 depending on jax x64 config.
// int64 little-endian: odd 32-bit words are all zero (values < 4096).
__global__ void rc_prep_vidx_kernel(const int* __restrict__ raw) {
    __shared__ int nz;
    if (threadIdx.x == 0) nz = 0;
    __syncthreads();
    if (threadIdx.x < 100 && raw[threadIdx.x] == 0) atomicAdd(&nz, 1);
    __syncthreads();
    bool is64 = (nz >= 40);
    if (threadIdx.x < 100)
        g_vidx[threadIdx.x] = is64 ? raw[2*threadIdx.x] : raw[threadIdx.x];
}

__global__ void rc_transpose_w_kernel(const float* __restrict__ w1,
                                      const float* __restrict__ w2) {
    int idx = blockIdx.x*256 + threadIdx.x;
    if (idx < 16384) {            // W1 [128,128]
        int j = idx >> 7, k = idx & 127;
        g_W1t[k*128 + j] = w1[idx];
    } else if (idx < 24576) {     // W2 [64,128]
        int t = idx - 16384;
        int j = t >> 7, k = t & 127;
        g_W2t[k*64 + j] = w2[t];
    }
}

// ---------------- fused conv1(3x3x3,128->32)+ReLU+conv2(1x1)+sigmoid-threshold ----------------
// Round-3 ncu: L1=73%, fma=30%, issue=36% -> the 1:1 LDS:FFMA2 ratio was the bottleneck
// (LDS structural floor binds at eff-4cyc/SMSP with nw>=4). Re-blocked: each thread owns
// 16 oc x 8 voxels (4 z-adjacent f32x2 pairs); 2 oc-groups per block (warp-uniform ->
// weight LDS.64 stays broadcast). LDS per FFMA2 drops 1.06 -> 0.375; FFMA2 floor
// (906M warp-ops, 3.06M cyc/SM) becomes binding.
// Tile: 16(x) * 4(y) * 16(z); 256 threads = 128 voxel-slots x 2 oc-groups.
__global__ __launch_bounds__(256, 1)
void rc_conv_mask_kernel(const float* __restrict__ in,
                         const float* __restrict__ w1,
                         const float* __restrict__ b1,
                         const float* __restrict__ w2,
                         const float* __restrict__ b2) {
    __shared__ float in_s[2*1944];    // [cl][lz(18)][ly(6)][lx(18)]
    __shared__ ull   w_s[2*27*32];    // [(cl*27+k)*32 + oc], value duplicated in both halves
    __shared__ float red[128][8];     // oc-group partial sums

    const int tid  = threadIdx.x;
    const int ocg  = tid >> 7;               // 0 or 1 (16 ocs each)
    const int slot = tid & 127;
    const int tx = slot & 15, ty = (slot >> 4) & 3, tz = slot >> 6;  // tz in {0,1}
    const int OC0 = ocg * 16;

    const int b  = blockIdx.z >> 2, zt = blockIdx.z & 3;
    const int x0 = blockIdx.x * 16, y0 = blockIdx.y * 4, z0 = zt * 16;

    const float* src = in + b * B_STRIDE;

    ull acc[16][4];
#pragma unroll
    for (int oc = 0; oc < 16; oc++)
#pragma unroll
        for (int p = 0; p < 4; p++) acc[oc][p] = 0ull;

    for (int cc0 = 0; cc0 < 128; cc0 += 2) {
        // stage input tile with halo (zero padded): 2 channels x 18x6x18
        for (int idx = tid; idx < 2*1944; idx += 256) {
            int cl = idx / 1944; int rem = idx - cl*1944;
            int lz = rem / 108;  int r2  = rem - lz*108;
            int ly = r2 / 18;    int lx  = r2 - ly*18;
            int gz = z0 - 1 + lz, gy = y0 - 1 + ly, gx = x0 - 1 + lx;
            float v = 0.f;
            if ((unsigned)gz < 64u && (unsigned)gy < 64u && (unsigned)gx < 64u)
                v = src[(cc0 + cl)*CH_STRIDE + gz*4096 + gy*64 + gx];
            in_s[idx] = v;
        }
        // stage weights (k fastest for coalescing), duplicated into both 32-bit halves
        for (int idx = tid; idx < 1728; idx += 256) {
            int oc = idx / 54; int kk = idx - oc*54;   // kk = cl*27 + k
            int cl = kk / 27;  int k  = kk - cl*27;
            unsigned u = __float_as_uint(w1[oc*3456 + (cc0 + cl)*27 + k]);
            w_s[kk*32 + oc] = ((ull)u << 32) | u;
        }
        __syncthreads();

#pragma unroll 1
        for (int cl = 0; cl < 2; cl++) {
            const float* cbase = &in_s[cl*1944 + (tz*8)*108 + ty*18 + tx];
            const ull*   wcl   = &w_s[cl*27*32];
#pragma unroll 1
            for (int kz = 0; kz < 3; kz++) {
#pragma unroll 1
                for (int ky = 0; ky < 3; ky++) {
                    const float* ip = cbase + kz*108 + ky*18;
                    const ull*   wk = wcl + (kz*9 + ky*3)*32 + OC0;
#pragma unroll
                    for (int kx = 0; kx < 3; kx++) {
                        ull av[4];
#pragma unroll
                        for (int p = 0; p < 4; p++) {
                            float a0 = ip[kx + (2*p)*108];
                            float a1 = ip[kx + (2*p+1)*108];
                            asm("mov.b64 %0, {%1, %2};"
                                : "=l"(av[p])
                                : "r"(__float_as_uint(a0)), "r"(__float_as_uint(a1)));
                        }
                        const ull* w = wk + kx*32;
#pragma unroll
                        for (int oc = 0; oc < 16; oc++) {
                            ull wv = w[oc];
#pragma unroll
                            for (int p = 0; p < 4; p++)
                                asm("fma.rn.f32x2 %0, %1, %2, %0;"
                                    : "+l"(acc[oc][p]) : "l"(av[p]), "l"(wv));
                        }
                    }
                }
            }
        }
        __syncthreads();
    }

    // epilogue: bias+ReLU, 1x1 conv2 partial over this thread's 16 ocs
    float vloc[8];
#pragma unroll
    for (int p = 0; p < 8; p++) vloc[p] = 0.f;
#pragma unroll
    for (int oc = 0; oc < 16; oc++) {
        float bb = b1[OC0 + oc], ww = w2[OC0 + oc];
#pragma unroll
        for (int p = 0; p < 4; p++) {
            float lo = __uint_as_float((unsigned)(acc[oc][p] & 0xffffffffu));
            float hi = __uint_as_float((unsigned)(acc[oc][p] >> 32));
            vloc[2*p]   += fmaxf(lo + bb, 0.f) * ww;
            vloc[2*p+1] += fmaxf(hi + bb, 0.f) * ww;
        }
    }
    if (ocg == 1) {
#pragma unroll
        for (int p = 0; p < 8; p++) red[slot][p] = vloc[p];
    }
    __syncthreads();
    if (ocg == 0) {
        float b2v = b2[0];
        int cnt = 0;
#pragma unroll
        for (int p = 0; p < 8; p++)
            cnt += (vloc[p] + red[slot][p] + b2v > SIG_THR) ? 1 : 0;
#pragma unroll
        for (int o = 16; o > 0; o >>= 1) cnt += __shfl_xor_sync(0xffffffffu, cnt, o);
        if ((tid & 31) == 0) {
            int patch = zt*16 + (y0 >> 4)*4 + (x0 >> 4);   // whole tile in one patch
            atomicAdd(&g_pcount[b*64 + patch], cnt);
        }
    }
}

// ---------------- per (which,b,channel,spatial-patch) means ----------------
__global__ void rc_patchmean_kernel(const float* __restrict__ a,
                                    const float* __restrict__ p) {
    int s = blockIdx.x, c = blockIdx.y;
    int which = blockIdx.z >> 1, b = blockIdx.z & 1;
    const float* src = (which == 0 ? a : p) + b*B_STRIDE + c*CH_STRIDE;
    int dp = s >> 4, hp = (s >> 2) & 3, wp = s & 3;
    const float* base = src + (dp*16)*4096 + (hp*16)*64 + wp*16;
    float sum = 0.f;
    for (int v = threadIdx.x; v < 4096; v += 128) {
        int pz = v >> 8, py = (v >> 4) & 15, px = v & 15;
        sum += base[pz*4096 + py*64 + px];
    }
    __shared__ float red[128];
    red[threadIdx.x] = sum; __syncthreads();
    for (int st = 64; st > 0; st >>= 1) {
        if (threadIdx.x < st) red[threadIdx.x] += red[threadIdx.x + st];
        __syncthreads();
    }
    if (threadIdx.x == 0) g_PM[which][b][c][s] = red[0] * (1.f/4096.f);
}

// ---------------- voxel gather: replicates the channel/patch-mixing view ----------------
// reference view(B,-1,C,P,P,P) mixes channels & spatial patches:
//   row (b,n) channel c' -> real channel 2n + (c'>>6), spatial patch c'&63
__global__ void rc_gather_vox_kernel(const float* __restrict__ a,
                                     const float* __restrict__ p) {
    int i = blockIdx.x, n = blockIdx.y;
    int which = blockIdx.z >> 1, b = blockIdx.z & 1;
    int c = threadIdx.x;                       // c' in [0,128)
    const float* src = (which == 0 ? a : p) + b*B_STRIDE;
    int v = g_vidx[i];
    int pz = v >> 8, py = (v >> 4) & 15, px = v & 15;
    int ch = 2*n + (c >> 6);
    int s  = c & 63;
    int z = (s >> 4)*16 + pz, y = ((s >> 2) & 3)*16 + py, x = (s & 3)*16 + px;
    int row = which*NROWS_VOX + (b*64 + n)*100 + i;
    g_X[row*128 + c] = src[ch*CH_STRIDE + z*4096 + y*64 + x];
}

__global__ void rc_gather_vec_kernel() {
    int n = blockIdx.x, b = blockIdx.y, which = blockIdx.z;
    int c = threadIdx.x;
    int row = ROW_VEC_A + which*128 + b*64 + n;
    g_X[row*128 + c] = g_PM[which][b][2*n + (c >> 6)][c & 63];
}

// ---------------- projector (128->128 ReLU ->64) + L2 normalize, 16 rows/block ----------------
__global__ __launch_bounds__(128)
void rc_projector_kernel(const float* __restrict__ b1v, const float* __restrict__ b2v) {
    __shared__ float Xs[16*128];
    __shared__ float Hs[16*128];
    __shared__ float Ys[16*64];
    __shared__ float nrm[16];
    int r0 = blockIdx.x * 16;
    int j = threadIdx.x;

    for (int idx = j; idx < 2048; idx += 128) Xs[idx] = g_X[r0*128 + idx];
    __syncthreads();
    {
        float acc[16];
        float bj = b1v[j];
#pragma unroll
        for (int r = 0; r < 16; r++) acc[r] = bj;
        for (int k = 0; k < 128; k++) {
            float w = g_W1t[k*128 + j];
#pragma unroll
            for (int r = 0; r < 16; r++) acc[r] += w * Xs[r*128 + k];
        }
#pragma unroll
        for (int r = 0; r < 16; r++) Hs[r*128 + j] = fmaxf(acc[r], 0.f);
    }
    __syncthreads();
    if (j < 64) {
        float acc[16];
        float bj = b2v[j];
#pragma unroll
        for (int r = 0; r < 16; r++) acc[r] = bj;
        for (int k = 0; k < 128; k++) {
            float w = g_W2t[k*64 + j];
#pragma unroll
            for (int r = 0; r < 16; r++) acc[r] += w * Hs[r*128 + k];
        }
#pragma unroll
        for (int r = 0; r < 16; r++) Ys[r*64 + j] = acc[r];
    }
    __syncthreads();
    if (j < 16) {
        float ss = 0.f;
#pragma unroll
        for (int d = 0; d < 64; d++) { float y = Ys[j*64 + d]; ss += y*y; }
        nrm[j] = 1.f / fmaxf(sqrtf(ss), 1e-12f);
    }
    __syncthreads();
    for (int idx = j; idx < 1024; idx += 128) {
        int r = idx >> 6;
        g_Y[(r0 + r)*64 + (idx & 63)] = Ys[idx] * nrm[r];
    }
}

// ---------------- voxel loss: 100x100 sim, online logsumexp, mean(lse - diag) ----------------
__global__ __launch_bounds__(128)
void rc_voxloss_kernel() {
    __shared__ float Ps[100*64];
    __shared__ float red[128];
    int bn = blockIdx.x;
    int rowA = bn*100, rowP = NROWS_VOX + bn*100;
    for (int idx = threadIdx.x; idx < 6400; idx += 128)
        Ps[idx] = g_Y[rowP*64 + idx];
    __syncthreads();
    int i = threadIdx.x;
    float contrib = 0.f;
    if (i < 100) {
        float areg[64];
        const float4* ar = (const float4*)&g_Y[(rowA + i)*64];
#pragma unroll
        for (int q = 0; q < 16; q++) {
            float4 t = ar[q];
            areg[4*q] = t.x; areg[4*q+1] = t.y; areg[4*q+2] = t.z; areg[4*q+3] = t.w;
        }
        float m = -INFINITY, ssum = 0.f, dv = 0.f;
        for (int jj = 0; jj < 100; jj++) {
            const float* pj = &Ps[jj*64];
            float v = 0.f;
#pragma unroll
            for (int d = 0; d < 64; d++) v += areg[d] * pj[d];
            v *= TEMP_INV;
            if (jj == i) dv = v;
            if (v > m) { ssum = ssum * __expf(m - v) + 1.0f; m = v; }
            else       { ssum += __expf(v - m); }
        }
        contrib = (m + __logf(ssum)) - dv;
    }
    red[threadIdx.x] = contrib; __syncthreads();
    for (int st = 64; st > 0; st >>= 1) {
        if (threadIdx.x < st) red[threadIdx.x] += red[threadIdx.x + st];
        __syncthreads();
    }
    if (threadIdx.x == 0) g_voxloss[bn] = red[0] * (1.f/100.f);
}

// ---------------- final combine ----------------
__global__ void rc_final_kernel(const float* __restrict__ lw, float* __restrict__ out) {
    __shared__ float rp[128], rv[128], rc[128];
    int bn = threadIdx.x;
    float ratio  = (float)g_pcount[bn] * (1.f/4096.f);
    float mvox   = ratio > 0.6f ? 1.f : 0.f;
    float mpatch = ratio < 0.4f ? 1.f : 0.f;
    float dot = 0.f;
    const float* ya = &g_Y[(ROW_VEC_A + bn)*64];
    const float* yp = &g_Y[(ROW_VEC_P + bn)*64];
#pragma unroll
    for (int d = 0; d < 64; d++) dot += ya[d] * yp[d];
    float pl = -dot * TEMP_INV;
    rp[bn] = pl * mpatch;
    rv[bn] = g_voxloss[bn] * mvox;
    rc[bn] = mpatch + mvox;
    __syncthreads();
    for (int st = 64; st > 0; st >>= 1) {
        if (bn < st) { rp[bn] += rp[bn+st]; rv[bn] += rv[bn+st]; rc[bn] += rc[bn+st]; }
        __syncthreads();
    }
    if (bn == 0) {
        float total = lw[0]*rp[0] + lw[1]*rv[0];
        float valid = rc[0];
        out[0] = (valid > 0.f) ? total / fmaxf(valid, 1.f) : 0.f;
    }
}

// ---------------- launch ----------------
extern "C" void kernel_launch(void* const* d_in, const int* in_sizes, int n_in,
                              void* d_out, int out_size) {
    const float* anchor   = (const float*)d_in[0];
    const float* positive = (const float*)d_in[1];
    const float* c1w = (const float*)d_in[2];
    const float* c1b = (const float*)d_in[3];
    const float* c2w = (const float*)d_in[4];
    const float* c2b = (const float*)d_in[5];
    const float* w1  = (const float*)d_in[6];
    const float* b1  = (const float*)d_in[7];
    const float* w2  = (const float*)d_in[8];
    const float* b2  = (const float*)d_in[9];
    const float* lw  = (const float*)d_in[10];
    const int*   vix = (const int*)d_in[11];   // int32 or int64; decoded on device

    rc_zero_kernel<<<1, 128>>>();
    rc_prep_vidx_kernel<<<1, 128>>>(vix);
    rc_transpose_w_kernel<<<96, 256>>>(w1, w2);

    rc_conv_mask_kernel<<<dim3(4, 16, 8), 256>>>(anchor, c1w, c1b, c2w, c2b);
    rc_patchmean_kernel<<<dim3(64, 128, 4), 128>>>(anchor, positive);
    rc_gather_vox_kernel<<<dim3(100, 64, 4), 128>>>(anchor, positive);
    rc_gather_vec_kernel<<<dim3(64, 2, 2), 128>>>();

    rc_projector_kernel<<<NROWS/16, 128>>>(b1, b2);
    rc_voxloss_kernel<<<128, 128>>>();
    rc_final_kernel<<<1, 128>>>(lw, (float*)d_out);
}

// round 17
// speedup vs baseline: 1.3238x; 1.0221x over previous
#include <cuda_runtime.h>
#include <math.h>

// ---------------- problem constants ----------------
#define B_STRIDE   (128*262144)   // per-batch stride in feats
#define CH_STRIDE  262144         // per-channel stride (64^3)
#define SIG_THR    (-1.0986122886681098f)  // ln(0.25/0.75): sigmoid(x)>0.25 <=> x>thr
#define TEMP_INV   10.0f

#define NROWS_VOX  12800          // 2*64*100 rows per (anchor|positive)
#define ROW_VEC_A  25600
#define ROW_VEC_P  25728
#define NROWS      25856          // 2*12800 + 2*128

typedef unsigned long long ull;

// ---------------- scratch (static device globals; no allocations) ----------------
__device__ float g_PM[2][2][128][64];   // [which][b][c][spatial_patch] patch means
__device__ int   g_pcount[128];         // [b*64 + spatial_patch] edge voxel counts
__device__ int   g_vidx[100];           // decoded voxel indices
__device__ float g_W1t[128*128];        // W1^T  (k-major)
__device__ float g_W2t[128*64];         // W2^T
__device__ float g_X[NROWS*128];        // projector inputs
__device__ float g_Y[NROWS*64];         // normalized projector outputs
__device__ float g_voxloss[128];        // per (b,n) voxel loss

// ---------------- tiny init kernels ----------------
__global__ void rc_zero_kernel() {
    if (threadIdx.x < 128) g_pcount[threadIdx.x] = 0;
}

// voxel_idx may arrive as int64 or int32 depending on jax x64 config.
// int64 little-endian: odd 32-bit words are all zero (values < 4096).
__global__ void rc_prep_vidx_kernel(const int* __restrict__ raw) {
    __shared__ int nz;
    if (threadIdx.x == 0) nz = 0;
    __syncthreads();
    if (threadIdx.x < 100 && raw[threadIdx.x] == 0) atomicAdd(&nz, 1);
    __syncthreads();
    bool is64 = (nz >= 40);
    if (threadIdx.x < 100)
        g_vidx[threadIdx.x] = is64 ? raw[2*threadIdx.x] : raw[threadIdx.x];
}

__global__ void rc_transpose_w_kernel(const float* __restrict__ w1,
                                      const float* __restrict__ w2) {
    int idx = blockIdx.x*256 + threadIdx.x;
    if (idx < 16384) {            // W1 [128,128]
        int j = idx >> 7, k = idx & 127;
        g_W1t[k*128 + j] = w1[idx];
    } else if (idx < 24576) {     // W2 [64,128]
        int t = idx - 16384;
        int j = t >> 7, k = t & 127;
        g_W2t[k*64 + j] = w2[t];
    }
}

// ---------------- fused conv1(3x3x3,128->32)+ReLU+conv2(1x1)+sigmoid-threshold ----------------
// R3:  L1=73% fma=30% -> LDS:FFMA2 1:1 was binding.
// R15: L1=43% fma=39% issue=36% regs=204 occ=12.5% -> LDS fixed, but 128 accumulator regs
//      forced 1x256thr CTA = 2 warps/SMSP; latency-exposed (matches cycle model: FMA busy
//      3.06M/7.3M cyc = 42%).  Pre-committed branch fired: occupancy fix.
// Now: 8 oc x 8 voxels per thread (acc = 64 regs), 512 threads = 128 voxel-slots x 4
//      oc-groups, __launch_bounds__(512,1) caps regs at 128 -> 16 warps/SM = 4/SMSP.
//      Per kx/SMSP: 4w x (32 FFMA2 + 16 LDS + ~6) = 216 issues vs >=256 FMA-bound cyc.
__global__ __launch_bounds__(512, 1)
void rc_conv_mask_kernel(const float* __restrict__ in,
                         const float* __restrict__ w1,
                         const float* __restrict__ b1,
                         const float* __restrict__ w2,
                         const float* __restrict__ b2) {
    __shared__ float in_s[2*1944];    // [cl][lz(18)][ly(6)][lx(18)]
    __shared__ ull   w_s[2*27*32];    // [(cl*27+k)*32 + oc], value duplicated in both halves
    __shared__ float red[3][128][8];  // partial sums from oc-groups 1..3

    const int tid  = threadIdx.x;
    const int ocg  = tid >> 7;               // 0..3 (8 ocs each)
    const int slot = tid & 127;
    const int tx = slot & 15, ty = (slot >> 4) & 3, tz = slot >> 6;  // tz in {0,1}
    const int OC0 = ocg * 8;

    const int b  = blockIdx.z >> 2, zt = blockIdx.z & 3;
    const int x0 = blockIdx.x * 16, y0 = blockIdx.y * 4, z0 = zt * 16;

    const float* src = in + b * B_STRIDE;

    ull acc[8][4];
#pragma unroll
    for (int oc = 0; oc < 8; oc++)
#pragma unroll
        for (int p = 0; p < 4; p++) acc[oc][p] = 0ull;

    for (int cc0 = 0; cc0 < 128; cc0 += 2) {
        // stage input tile with halo (zero padded): 2 channels x 18x6x18
        for (int idx = tid; idx < 2*1944; idx += 512) {
            int cl = idx / 1944; int rem = idx - cl*1944;
            int lz = rem / 108;  int r2  = rem - lz*108;
            int ly = r2 / 18;    int lx  = r2 - ly*18;
            int gz = z0 - 1 + lz, gy = y0 - 1 + ly, gx = x0 - 1 + lx;
            float v = 0.f;
            if ((unsigned)gz < 64u && (unsigned)gy < 64u && (unsigned)gx < 64u)
                v = src[(cc0 + cl)*CH_STRIDE + gz*4096 + gy*64 + gx];
            in_s[idx] = v;
        }
        // stage weights (k fastest for coalescing), duplicated into both 32-bit halves
        for (int idx = tid; idx < 1728; idx += 512) {
            int oc = idx / 54; int kk = idx - oc*54;   // kk = cl*27 + k
            int cl = kk / 27;  int k  = kk - cl*27;
            unsigned u = __float_as_uint(w1[oc*3456 + (cc0 + cl)*27 + k]);
            w_s[kk*32 + oc] = ((ull)u << 32) | u;
        }
        __syncthreads();

#pragma unroll 1
        for (int cl = 0; cl < 2; cl++) {
            const float* cbase = &in_s[cl*1944 + (tz*8)*108 + ty*18 + tx];
            const ull*   wcl   = &w_s[cl*27*32];
#pragma unroll 1
            for (int kz = 0; kz < 3; kz++) {
#pragma unroll 1
                for (int ky = 0; ky < 3; ky++) {
                    const float* ip = cbase + kz*108 + ky*18;
                    const ull*   wk = wcl + (kz*9 + ky*3)*32 + OC0;
#pragma unroll
                    for (int kx = 0; kx < 3; kx++) {
                        ull av[4];
#pragma unroll
                        for (int p = 0; p < 4; p++) {
                            float a0 = ip[kx + (2*p)*108];
                            float a1 = ip[kx + (2*p+1)*108];
                            asm("mov.b64 %0, {%1, %2};"
                                : "=l"(av[p])
                                : "r"(__float_as_uint(a0)), "r"(__float_as_uint(a1)));
                        }
                        const ull* w = wk + kx*32;
#pragma unroll
                        for (int oc = 0; oc < 8; oc++) {
                            ull wv = w[oc];
#pragma unroll
                            for (int p = 0; p < 4; p++)
                                asm("fma.rn.f32x2 %0, %1, %2, %0;"
                                    : "+l"(acc[oc][p]) : "l"(av[p]), "l"(wv));
                        }
                    }
                }
            }
        }
        __syncthreads();
    }

    // epilogue: bias+ReLU, 1x1 conv2 partial over this thread's 8 ocs
    float vloc[8];
#pragma unroll
    for (int p = 0; p < 8; p++) vloc[p] = 0.f;
#pragma unroll
    for (int oc = 0; oc < 8; oc++) {
        float bb = b1[OC0 + oc], ww = w2[OC0 + oc];
#pragma unroll
        for (int p = 0; p < 4; p++) {
            float lo = __uint_as_float((unsigned)(acc[oc][p] & 0xffffffffu));
            float hi = __uint_as_float((unsigned)(acc[oc][p] >> 32));
            vloc[2*p]   += fmaxf(lo + bb, 0.f) * ww;
            vloc[2*p+1] += fmaxf(hi + bb, 0.f) * ww;
        }
    }
    if (ocg > 0) {
#pragma unroll
        for (int p = 0; p < 8; p++) red[ocg-1][slot][p] = vloc[p];
    }
    __syncthreads();
    if (ocg == 0) {
        float b2v = b2[0];
        int cnt = 0;
#pragma unroll
        for (int p = 0; p < 8; p++) {
            float v = vloc[p] + red[0][slot][p] + red[1][slot][p] + red[2][slot][p] + b2v;
            cnt += (v > SIG_THR) ? 1 : 0;
        }
#pragma unroll
        for (int o = 16; o > 0; o >>= 1) cnt += __shfl_xor_sync(0xffffffffu, cnt, o);
        if ((tid & 31) == 0) {
            int patch = zt*16 + (y0 >> 4)*4 + (x0 >> 4);   // whole tile in one patch
            atomicAdd(&g_pcount[b*64 + patch], cnt);
        }
    }
}

// ---------------- per (which,b,channel,spatial-patch) means ----------------
__global__ void rc_patchmean_kernel(const float* __restrict__ a,
                                    const float* __restrict__ p) {
    int s = blockIdx.x, c = blockIdx.y;
    int which = blockIdx.z >> 1, b = blockIdx.z & 1;
    const float* src = (which == 0 ? a : p) + b*B_STRIDE + c*CH_STRIDE;
    int dp = s >> 4, hp = (s >> 2) & 3, wp = s & 3;
    const float* base = src + (dp*16)*4096 + (hp*16)*64 + wp*16;
    float sum = 0.f;
    for (int v = threadIdx.x; v < 4096; v += 128) {
        int pz = v >> 8, py = (v >> 4) & 15, px = v & 15;
        sum += base[pz*4096 + py*64 + px];
    }
    __shared__ float red[128];
    red[threadIdx.x] = sum; __syncthreads();
    for (int st = 64; st > 0; st >>= 1) {
        if (threadIdx.x < st) red[threadIdx.x] += red[threadIdx.x + st];
        __syncthreads();
    }
    if (threadIdx.x == 0) g_PM[which][b][c][s] = red[0] * (1.f/4096.f);
}

// ---------------- voxel gather: replicates the channel/patch-mixing view ----------------
// reference view(B,-1,C,P,P,P) mixes channels & spatial patches:
//   row (b,n) channel c' -> real channel 2n + (c'>>6), spatial patch c'&63
__global__ void rc_gather_vox_kernel(const float* __restrict__ a,
                                     const float* __restrict__ p) {
    int i = blockIdx.x, n = blockIdx.y;
    int which = blockIdx.z >> 1, b = blockIdx.z & 1;
    int c = threadIdx.x;                       // c' in [0,128)
    const float* src = (which == 0 ? a : p) + b*B_STRIDE;
    int v = g_vidx[i];
    int pz = v >> 8, py = (v >> 4) & 15, px = v & 15;
    int ch = 2*n + (c >> 6);
    int s  = c & 63;
    int z = (s >> 4)*16 + pz, y = ((s >> 2) & 3)*16 + py, x = (s & 3)*16 + px;
    int row = which*NROWS_VOX + (b*64 + n)*100 + i;
    g_X[row*128 + c] = src[ch*CH_STRIDE + z*4096 + y*64 + x];
}

__global__ void rc_gather_vec_kernel() {
    int n = blockIdx.x, b = blockIdx.y, which = blockIdx.z;
    int c = threadIdx.x;
    int row = ROW_VEC_A + which*128 + b*64 + n;
    g_X[row*128 + c] = g_PM[which][b][2*n + (c >> 6)][c & 63];
}

// ---------------- projector (128->128 ReLU ->64) + L2 normalize, 16 rows/block ----------------
__global__ __launch_bounds__(128)
void rc_projector_kernel(const float* __restrict__ b1v, const float* __restrict__ b2v) {
    __shared__ float Xs[16*128];
    __shared__ float Hs[16*128];
    __shared__ float Ys[16*64];
    __shared__ float nrm[16];
    int r0 = blockIdx.x * 16;
    int j = threadIdx.x;

    for (int idx = j; idx < 2048; idx += 128) Xs[idx] = g_X[r0*128 + idx];
    __syncthreads();
    {
        float acc[16];
        float bj = b1v[j];
#pragma unroll
        for (int r = 0; r < 16; r++) acc[r] = bj;
        for (int k = 0; k < 128; k++) {
            float w = g_W1t[k*128 + j];
#pragma unroll
            for (int r = 0; r < 16; r++) acc[r] += w * Xs[r*128 + k];
        }
#pragma unroll
        for (int r = 0; r < 16; r++) Hs[r*128 + j] = fmaxf(acc[r], 0.f);
    }
    __syncthreads();
    if (j < 64) {
        float acc[16];
        float bj = b2v[j];
#pragma unroll
        for (int r = 0; r < 16; r++) acc[r] = bj;
        for (int k = 0; k < 128; k++) {
            float w = g_W2t[k*64 + j];
#pragma unroll
            for (int r = 0; r < 16; r++) acc[r] += w * Hs[r*128 + k];
        }
#pragma unroll
        for (int r = 0; r < 16; r++) Ys[r*64 + j] = acc[r];
    }
    __syncthreads();
    if (j < 16) {
        float ss = 0.f;
#pragma unroll
        for (int d = 0; d < 64; d++) { float y = Ys[j*64 + d]; ss += y*y; }
        nrm[j] = 1.f / fmaxf(sqrtf(ss), 1e-12f);
    }
    __syncthreads();
    for (int idx = j; idx < 1024; idx += 128) {
        int r = idx >> 6;
        g_Y[(r0 + r)*64 + (idx & 63)] = Ys[idx] * nrm[r];
    }
}

// ---------------- voxel loss: 100x100 sim, online logsumexp, mean(lse - diag) ----------------
__global__ __launch_bounds__(128)
void rc_voxloss_kernel() {
    __shared__ float Ps[100*64];
    __shared__ float red[128];
    int bn = blockIdx.x;
    int rowA = bn*100, rowP = NROWS_VOX + bn*100;
    for (int idx = threadIdx.x; idx < 6400; idx += 128)
        Ps[idx] = g_Y[rowP*64 + idx];
    __syncthreads();
    int i = threadIdx.x;
    float contrib = 0.f;
    if (i < 100) {
        float areg[64];
        const float4* ar = (const float4*)&g_Y[(rowA + i)*64];
#pragma unroll
        for (int q = 0; q < 16; q++) {
            float4 t = ar[q];
            areg[4*q] = t.x; areg[4*q+1] = t.y; areg[4*q+2] = t.z; areg[4*q+3] = t.w;
        }
        float m = -INFINITY, ssum = 0.f, dv = 0.f;
        for (int jj = 0; jj < 100; jj++) {
            const float* pj = &Ps[jj*64];
            float v = 0.f;
#pragma unroll
            for (int d = 0; d < 64; d++) v += areg[d] * pj[d];
            v *= TEMP_INV;
            if (jj == i) dv = v;
            if (v > m) { ssum = ssum * __expf(m - v) + 1.0f; m = v; }
            else       { ssum += __expf(v - m); }
        }
        contrib = (m + __logf(ssum)) - dv;
    }
    red[threadIdx.x] = contrib; __syncthreads();
    for (int st = 64; st > 0; st >>= 1) {
        if (threadIdx.x < st) red[threadIdx.x] += red[threadIdx.x + st];
        __syncthreads();
    }
    if (threadIdx.x == 0) g_voxloss[bn] = red[0] * (1.f/100.f);
}

// ---------------- final combine ----------------
__global__ void rc_final_kernel(const float* __restrict__ lw, float* __restrict__ out) {
    __shared__ float rp[128], rv[128], rc[128];
    int bn = threadIdx.x;
    float ratio  = (float)g_pcount[bn] * (1.f/4096.f);
    float mvox   = ratio > 0.6f ? 1.f : 0.f;
    float mpatch = ratio < 0.4f ? 1.f : 0.f;
    float dot = 0.f;
    const float* ya = &g_Y[(ROW_VEC_A + bn)*64];
    const float* yp = &g_Y[(ROW_VEC_P + bn)*64];
#pragma unroll
    for (int d = 0; d < 64; d++) dot += ya[d] * yp[d];
    float pl = -dot * TEMP_INV;
    rp[bn] = pl * mpatch;
    rv[bn] = g_voxloss[bn] * mvox;
    rc[bn] = mpatch + mvox;
    __syncthreads();
    for (int st = 64; st > 0; st >>= 1) {
        if (bn < st) { rp[bn] += rp[bn+st]; rv[bn] += rv[bn+st]; rc[bn] += rc[bn+st]; }
        __syncthreads();
    }
    if (bn == 0) {
        float total = lw[0]*rp[0] + lw[1]*rv[0];
        float valid = rc[0];
        out[0] = (valid > 0.f) ? total / fmaxf(valid, 1.f) : 0.f;
    }
}

// ---------------- launch ----------------
extern "C" void kernel_launch(void* const* d_in, const int* in_sizes, int n_in,
                              void* d_out, int out_size) {
    const float* anchor   = (const float*)d_in[0];
    const float* positive = (const float*)d_in[1];
    const float* c1w = (const float*)d_in[2];
    const float* c1b = (const float*)d_in[3];
    const float* c2w = (const float*)d_in[4];
    const float* c2b = (const float*)d_in[5];
    const float* w1  = (const float*)d_in[6];
    const float* b1  = (const float*)d_in[7];
    const float* w2  = (const float*)d_in[8];
    const float* b2  = (const float*)d_in[9];
    const float* lw  = (const float*)d_in[10];
    const int*   vix = (const int*)d_in[11];   // int32 or int64; decoded on device

    rc_zero_kernel<<<1, 128>>>();
    rc_prep_vidx_kernel<<<1, 128>>>(vix);
    rc_transpose_w_kernel<<<96, 256>>>(w1, w2);

    rc_conv_mask_kernel<<<dim3(4, 16, 8), 512>>>(anchor, c1w, c1b, c2w, c2b);
    rc_patchmean_kernel<<<dim3(64, 128, 4), 128>>>(anchor, positive);
    rc_gather_vox_kernel<<<dim3(100, 64, 4), 128>>>(anchor, positive);
    rc_gather_vec_kernel<<<dim3(64, 2, 2), 128>>>();

    rc_projector_kernel<<<NROWS/16, 128>>>(b1, b2);
    rc_voxloss_kernel<<<128, 128>>>();
    rc_final_kernel<<<1, 128>>>(lw, (float*)d_out);
}